// round 8
// baseline (speedup 1.0000x reference)
#include <cuda_runtime.h>
#include <cstdint>
#include <cstddef>

#define BQ    2048
#define NTOK  98
#define DIMC  256
#define NHEAD 8
#define HD    32
#define NWIN  64
#define QK_SCALE 0.17677669529663687f   // 32^-0.5

#define NN2   (NTOK*NTOK)               // 9604
#define QKV_ELEMS ((size_t)BQ*NHEAD*NTOK*HD)   // 51,380,224

// ---------------- scratch (static device globals; no cudaMalloc allowed) ----
__device__ float g_q[QKV_ELEMS];
__device__ float g_k[QKV_ELEMS];
__device__ float g_v[QKV_ELEMS];
__device__ float g_o[(size_t)BQ*NTOK*DIMC];
__device__ float g_bias[NHEAD*NN2];
__device__ float g_wt_qkv[768*256];     // qkv_w transposed [n][k], tf32-rounded
__device__ float g_wt_proj[256*256];    // proj_w transposed [n][k], tf32-rounded

// ======================= helpers =============================================
__device__ __forceinline__ uint32_t smem_to_u32(const void* p) {
    uint32_t a;
    asm("{ .reg .u64 t; cvta.to.shared.u64 t, %1; cvt.u32.u64 %0, t; }"
        : "=r"(a) : "l"(p));
    return a;
}
__device__ __forceinline__ void cp_async16(uint32_t dst, const void* src) {
    asm volatile("cp.async.cg.shared.global [%0], [%1], 16;"
                 :: "r"(dst), "l"(src) : "memory");
}
#define CP_COMMIT() asm volatile("cp.async.commit_group;" ::: "memory")
#define CP_WAIT(n)  asm volatile("cp.async.wait_group %0;" :: "n"(n) : "memory")

// tf32 warp MMA: D(16x8) += A(16x8) * B(8x8)
__device__ __forceinline__ void mma_tf32(float* d, const uint32_t* a, const uint32_t* b) {
    asm volatile(
        "mma.sync.aligned.m16n8k8.row.col.f32.tf32.tf32.f32 "
        "{%0,%1,%2,%3}, {%4,%5,%6,%7}, {%8,%9}, {%0,%1,%2,%3};"
        : "+f"(d[0]), "+f"(d[1]), "+f"(d[2]), "+f"(d[3])
        : "r"(a[0]), "r"(a[1]), "r"(a[2]), "r"(a[3]), "r"(b[0]), "r"(b[1]));
}

// fp32 -> tf32 round-to-nearest (unbiased).
__device__ __forceinline__ uint32_t to_tf32(float f) {
    uint32_t h;
    asm("cvt.rna.tf32.f32 %0, %1;" : "=r"(h) : "f"(f));
    return h;
}
__device__ __forceinline__ float round_tf32(float f) {
    return __uint_as_float(to_tf32(f));
}

// ---------------- kernel: transpose + tf32-round weights --------------------
__global__ void transpose_w_kernel(const float* __restrict__ W, int N, int which)
{
    __shared__ float t[32][33];
    float* Wt = which ? g_wt_proj : g_wt_qkv;
    int n0 = blockIdx.x * 32, k0 = blockIdx.y * 32;
    int tx = threadIdx.x, ty = threadIdx.y;    // 32 x 8
    #pragma unroll
    for (int j = 0; j < 4; ++j)
        t[ty + j*8][tx] = W[(size_t)(k0 + ty + j*8) * N + n0 + tx];
    __syncthreads();
    #pragma unroll
    for (int j = 0; j < 4; ++j)
        Wt[(size_t)(n0 + ty + j*8) * 256 + k0 + tx] = round_tf32(t[tx][ty + j*8]);
}

// ---------------- kernel: build per-head relative-position bias -------------
__global__ void bias_build_kernel(const float* __restrict__ table,
                                  const int*   __restrict__ rel)
{
    int t = blockIdx.x * blockDim.x + threadIdx.x;
    if (t < NHEAD * NN2) {
        int h  = t / NN2;
        int ij = t - h * NN2;
        g_bias[t] = table[rel[ij] * NHEAD + h];
    }
}

// ---------------- 1xTF32 mma.sync GEMM: 128x128 tile, K=256 -----------------
#define GPITCH 36
#define TILE_F (128 * GPITCH)                 // 4608 floats
#define BUF_F  (2 * TILE_F)                   // 9216 floats per buffer
#define GEMM_SMEM (2 * BUF_F * 4)             // 73728 bytes

template<bool IS_QKV, bool CVT_A>
__global__ void __launch_bounds__(256, 2)
gemm_mma_kernel(const float* __restrict__ Aq,   // QKV: x; proj: unused
                const float* __restrict__ bias,
                float* __restrict__ out)        // proj: d_out; QKV: unused
{
    extern __shared__ float smf[];
    uint32_t sb = smem_to_u32(smf);
    const int tid = threadIdx.x;
    const int wid = tid >> 5, lane = tid & 31;
    const int g = lane >> 2, tg = lane & 3;
    const int bm = blockIdx.x * 128;
    const int bn = blockIdx.y * 128;

    const float* A  = IS_QKV ? Aq : g_o;
    const float* Bt = IS_QKV ? g_wt_qkv : g_wt_proj;
    const int K = 256;

    const int r_  = tid >> 3;
    const int c4_ = tid & 7;

    float acc[4][4][4];
    #pragma unroll
    for (int am = 0; am < 4; ++am)
        #pragma unroll
        for (int an = 0; an < 4; ++an)
            #pragma unroll
            for (int j = 0; j < 4; ++j) acc[am][an][j] = 0.0f;

    auto issue = [&](int c, int buf) {
        int k0 = c * 32;
        uint32_t base = sb + (uint32_t)buf * (BUF_F * 4);
        #pragma unroll
        for (int i = 0; i < 4; ++i) {
            int r = r_ + i * 32;
            cp_async16(base + (uint32_t)(r * GPITCH * 4 + c4_ * 16),
                       A + (size_t)(bm + r) * K + k0 + c4_ * 4);
        }
        #pragma unroll
        for (int i = 0; i < 4; ++i) {
            int r = r_ + i * 32;
            cp_async16(base + (uint32_t)(TILE_F * 4 + r * GPITCH * 4 + c4_ * 16),
                       Bt + (size_t)(bn + r) * K + k0 + c4_ * 4);
        }
    };

    issue(0, 0);
    CP_COMMIT();

    const int mw = (wid >> 2) * 64;
    const int nw = (wid & 3) * 32;

    #pragma unroll 1
    for (int c = 0; c < 8; ++c) {
        if (c + 1 < 8) { issue(c + 1, (c + 1) & 1); CP_COMMIT(); CP_WAIT(1); }
        else           { CP_WAIT(0); }
        __syncthreads();

        const float* As = smf + (c & 1) * BUF_F;
        const float* Bs = As + TILE_F;

        #pragma unroll
        for (int s = 0; s < 4; ++s) {
            int k0 = s * 8 + tg;
            uint32_t b[4][2];
            #pragma unroll
            for (int an = 0; an < 4; ++an) {
                int base = (nw + 8 * an + g) * GPITCH + k0;
                b[an][0] = __float_as_uint(Bs[base]);      // pre-rounded
                b[an][1] = __float_as_uint(Bs[base + 4]);
            }
            #pragma unroll
            for (int am = 0; am < 4; ++am) {
                int base = (mw + 16 * am + g) * GPITCH + k0;
                uint32_t a[4];
                if (CVT_A) {
                    a[0] = to_tf32(As[base]);
                    a[1] = to_tf32(As[base + 8 * GPITCH]);
                    a[2] = to_tf32(As[base + 4]);
                    a[3] = to_tf32(As[base + 8 * GPITCH + 4]);
                } else {
                    a[0] = __float_as_uint(As[base]);
                    a[1] = __float_as_uint(As[base + 8 * GPITCH]);
                    a[2] = __float_as_uint(As[base + 4]);
                    a[3] = __float_as_uint(As[base + 8 * GPITCH + 4]);
                }
                #pragma unroll
                for (int an = 0; an < 4; ++an)
                    mma_tf32(acc[am][an], a, b[an]);
            }
        }
        __syncthreads();
    }

    // -------- epilogue --------
    #pragma unroll
    for (int am = 0; am < 4; ++am) {
        #pragma unroll
        for (int half = 0; half < 2; ++half) {
            int m = bm + mw + 16 * am + g + 8 * half;
            if (IS_QKV) {
                int bwin = m / NTOK;
                int nn   = m - bwin * NTOK;
                #pragma unroll
                for (int an = 0; an < 4; ++an) {
                    int gcol = bn + nw + 8 * an + 2 * tg;
                    int sel  = gcol >> 8;
                    int h    = (gcol >> 5) & 7;
                    int d    = gcol & 31;
                    float* dst = (sel == 0 ? g_q : (sel == 1 ? g_k : g_v))
                               + (((size_t)bwin * NHEAD + h) * NTOK + nn) * HD + d;
                    float sc = (sel == 0) ? QK_SCALE : 1.0f;
                    float2 v;
                    v.x = round_tf32((acc[am][an][2*half+0] + bias[gcol+0]) * sc);
                    v.y = round_tf32((acc[am][an][2*half+1] + bias[gcol+1]) * sc);
                    *(float2*)dst = v;
                }
            } else {
                #pragma unroll
                for (int an = 0; an < 4; ++an) {
                    int gcol = bn + nw + 8 * an + 2 * tg;
                    float2 v;
                    v.x = acc[am][an][2*half+0] + bias[gcol+0];
                    v.y = acc[am][an][2*half+1] + bias[gcol+1];
                    *(float2*)(out + (size_t)m * DIMC + gcol) = v;
                }
            }
        }
    }
}

// ---------------- kernel: mma.sync windowed attention ------------------------
// smem floats: Qs/Vt region [0,4032), Ks [4032,7776), Ss [7776,20768)
// Q/K pitch 36; S and Vt pitch 116 (20g+tg mod 32 covers all banks).
#define AQ_OFF 0
#define AK_OFF 4032
#define AS_OFF 7776
#define PS 116
#define ATTN_SMEM_BYTES (20768 * 4)     // 83072

__global__ void __launch_bounds__(256) attn_mma_kernel(const float* __restrict__ mask)
{
    extern __shared__ float sm[];
    float* Qs = sm + AQ_OFF;            // reused for V^T after QK
    float* Ks = sm + AK_OFF;
    float* Ss = sm + AS_OFF;

    int bid = blockIdx.x;
    int b = bid >> 3, h = bid & 7;
    int w = b & (NWIN - 1);
    int tid = threadIdx.x;
    int wid = tid >> 5, lane = tid & 31;
    int g = lane >> 2, tg = lane & 3;

    const float* qp = g_q + (size_t)bid * (NTOK * HD);
    const float* kp = g_k + (size_t)bid * (NTOK * HD);
    const float* vp = g_v + (size_t)bid * (NTOK * HD);

    // load Q, K (98x32, pitch 36); zero S k-pad cols 98..111 (all 112 rows)
    for (int t = tid; t < 784; t += 256) {
        float4 q4 = ((const float4*)qp)[t];
        float4 k4 = ((const float4*)kp)[t];
        int i = t >> 3, seg = (t & 7) * 4;
        *(float4*)&Qs[i*36 + seg] = q4;
        *(float4*)&Ks[i*36 + seg] = k4;
    }
    for (int t = tid; t < 1568; t += 256) {
        int r = t / 14, c = 98 + (t % 14);
        Ss[r*PS + c] = 0.0f;
    }
    __syncthreads();

    // ---- S = Q K^T : warps 0..6 own m-tiles (rows 16w..16w+15) ----
    if (wid < 7) {
        float acc[13][4];
        #pragma unroll
        for (int nt = 0; nt < 13; ++nt)
            #pragma unroll
            for (int j = 0; j < 4; ++j) acc[nt][j] = 0.0f;

        int mrow = wid * 16 + g;
        #pragma unroll
        for (int kt = 0; kt < 4; ++kt) {
            const float* qb = Qs + mrow*36 + kt*8 + tg;
            uint32_t a[4];
            a[0] = __float_as_uint(qb[0]);
            a[1] = __float_as_uint(qb[8*36]);
            a[2] = __float_as_uint(qb[4]);
            a[3] = __float_as_uint(qb[8*36 + 4]);
            #pragma unroll
            for (int nt = 0; nt < 13; ++nt) {
                const float* kb = Ks + (nt*8 + g)*36 + kt*8 + tg;
                uint32_t bb[2];
                bb[0] = __float_as_uint(kb[0]);
                bb[1] = __float_as_uint(kb[4]);
                mma_tf32(acc[nt], a, bb);
            }
        }

        // D + bias + mask -> S (guard row<98, col<98)
        const float* bp = g_bias + h * NN2;
        const float* mp = mask + w * NN2;
        #pragma unroll
        for (int nt = 0; nt < 13; ++nt) {
            int c0 = nt*8 + 2*tg;
            if (c0 < 98) {
                #pragma unroll
                for (int hh = 0; hh < 2; ++hh) {
                    int r = wid*16 + g + 8*hh;
                    if (r < 98) {
                        float2 bv = *(const float2*)(bp + r*NTOK + c0);
                        float2 mv = *(const float2*)(mp + r*NTOK + c0);
                        Ss[r*PS + c0]     = acc[nt][2*hh+0] + bv.x + mv.x;
                        Ss[r*PS + c0 + 1] = acc[nt][2*hh+1] + bv.y + mv.y;
                    }
                }
            }
        }
    }
    __syncthreads();

    // ---- load V transposed into Qs region (pitch 116); zero k-pad cols ----
    for (int t = tid; t < 3136; t += 256) {
        int tok = t >> 5, d = t & 31;
        Qs[d*PS + tok] = vp[t];
    }
    for (int t = tid; t < 448; t += 256) {
        int d = t / 14, c = 98 + (t % 14);
        Qs[d*PS + c] = 0.0f;
    }

    // ---- softmax over S rows (writes tf32-rounded P) ----
    for (int r = wid; r < NTOK; r += 8) {
        float* row = Ss + r * PS;
        float v0 = row[lane];
        float v1 = row[32 + lane];
        float v2 = row[64 + lane];
        float v3 = (lane < 2) ? row[96 + lane] : -1e30f;
        float mx = fmaxf(fmaxf(v0, v1), fmaxf(v2, v3));
        #pragma unroll
        for (int o = 16; o > 0; o >>= 1) mx = fmaxf(mx, __shfl_xor_sync(0xffffffffu, mx, o));
        float e0 = __expf(v0 - mx), e1 = __expf(v1 - mx), e2 = __expf(v2 - mx);
        float e3 = (lane < 2) ? __expf(v3 - mx) : 0.0f;
        float sum = e0 + e1 + e2 + e3;
        #pragma unroll
        for (int o = 16; o > 0; o >>= 1) sum += __shfl_xor_sync(0xffffffffu, sum, o);
        float inv = 1.0f / sum;
        row[lane]      = round_tf32(e0 * inv);
        row[32 + lane] = round_tf32(e1 * inv);
        row[64 + lane] = round_tf32(e2 * inv);
        if (lane < 2) row[96 + lane] = round_tf32(e3 * inv);
    }
    __syncthreads();

    // ---- O = P V : warps 0..6, 4 n-tiles (dims) x 14 k-steps (tokens) ----
    if (wid < 7) {
        float oacc[4][4];
        #pragma unroll
        for (int nt = 0; nt < 4; ++nt)
            #pragma unroll
            for (int j = 0; j < 4; ++j) oacc[nt][j] = 0.0f;

        int mrow = wid * 16 + g;
        #pragma unroll
        for (int kt = 0; kt < 14; ++kt) {
            const float* pb = Ss + mrow*PS + kt*8 + tg;
            uint32_t a[4];
            a[0] = __float_as_uint(pb[0]);
            a[1] = __float_as_uint(pb[8*PS]);
            a[2] = __float_as_uint(pb[4]);
            a[3] = __float_as_uint(pb[8*PS + 4]);
            #pragma unroll
            for (int nt = 0; nt < 4; ++nt) {
                const float* vb = Qs + (nt*8 + g)*PS + kt*8 + tg;
                uint32_t bb[2];
                bb[0] = __float_as_uint(vb[0]);
                bb[1] = __float_as_uint(vb[4]);
                mma_tf32(oacc[nt], a, bb);
            }
        }

        float* op = g_o + (size_t)b * NTOK * DIMC + h * HD;
        #pragma unroll
        for (int nt = 0; nt < 4; ++nt) {
            int d0 = nt*8 + 2*tg;
            #pragma unroll
            for (int hh = 0; hh < 2; ++hh) {
                int r = wid*16 + g + 8*hh;
                if (r < NTOK) {
                    float2 v;
                    v.x = round_tf32(oacc[nt][2*hh+0]);   // pre-round for proj A
                    v.y = round_tf32(oacc[nt][2*hh+1]);
                    *(float2*)(op + (size_t)r * DIMC + d0) = v;
                }
            }
        }
    }
}

// ---------------- launch -----------------------------------------------------
extern "C" void kernel_launch(void* const* d_in, const int* in_sizes, int n_in,
                              void* d_out, int out_size)
{
    const float* x          = (const float*)d_in[0];
    const float* mask       = (const float*)d_in[1];
    const float* qkv_w      = (const float*)d_in[2];
    const float* qkv_b      = (const float*)d_in[3];
    const float* proj_w     = (const float*)d_in[4];
    const float* proj_b     = (const float*)d_in[5];
    const float* bias_table = (const float*)d_in[6];
    const int*   rel_index  = (const int*)d_in[7];
    float* out = (float*)d_out;

    cudaFuncSetAttribute((const void*)gemm_mma_kernel<true, true>,
                         cudaFuncAttributeMaxDynamicSharedMemorySize, GEMM_SMEM);
    cudaFuncSetAttribute((const void*)gemm_mma_kernel<false, false>,
                         cudaFuncAttributeMaxDynamicSharedMemorySize, GEMM_SMEM);
    cudaFuncSetAttribute((const void*)attn_mma_kernel,
                         cudaFuncAttributeMaxDynamicSharedMemorySize, ATTN_SMEM_BYTES);

    transpose_w_kernel<<<dim3(24, 8), dim3(32, 8)>>>(qkv_w, 768, 0);
    transpose_w_kernel<<<dim3(8, 8),  dim3(32, 8)>>>(proj_w, 256, 1);
    bias_build_kernel<<<(NHEAD * NN2 + 255) / 256, 256>>>(bias_table, rel_index);

    gemm_mma_kernel<true, true><<<dim3(1568, 6), 256, GEMM_SMEM>>>(x, qkv_b, nullptr);

    attn_mma_kernel<<<BQ * NHEAD, 256, ATTN_SMEM_BYTES>>>(mask);

    gemm_mma_kernel<false, false><<<dim3(1568, 2), 256, GEMM_SMEM>>>(nullptr, proj_b, out);
}

// round 9
// speedup vs baseline: 1.0757x; 1.0757x over previous
#include <cuda_runtime.h>
#include <cstdint>
#include <cstddef>

#define BQ    2048
#define NTOK  98
#define DIMC  256
#define NHEAD 8
#define HD    32
#define NWIN  64
#define QK_SCALE 0.17677669529663687f   // 32^-0.5

#define NN2   (NTOK*NTOK)               // 9604
#define QKV_ELEMS ((size_t)BQ*NHEAD*NTOK*HD)   // 51,380,224

// ---------------- scratch (static device globals; no cudaMalloc allowed) ----
__device__ float g_q[QKV_ELEMS];
__device__ float g_k[QKV_ELEMS];
__device__ float g_v[QKV_ELEMS];
__device__ float g_o[(size_t)BQ*NTOK*DIMC];
__device__ float g_bias[NHEAD*NN2];
__device__ float g_wt_qkv[768*256];     // qkv_w transposed [n][k], tf32-rounded
__device__ float g_wt_proj[256*256];    // proj_w transposed [n][k], tf32-rounded

// ======================= helpers =============================================
__device__ __forceinline__ uint32_t smem_to_u32(const void* p) {
    uint32_t a;
    asm("{ .reg .u64 t; cvta.to.shared.u64 t, %1; cvt.u32.u64 %0, t; }"
        : "=r"(a) : "l"(p));
    return a;
}
__device__ __forceinline__ void cp_async16(uint32_t dst, const void* src) {
    asm volatile("cp.async.cg.shared.global [%0], [%1], 16;"
                 :: "r"(dst), "l"(src) : "memory");
}
#define CP_COMMIT() asm volatile("cp.async.commit_group;" ::: "memory")
#define CP_WAIT(n)  asm volatile("cp.async.wait_group %0;" :: "n"(n) : "memory")

// tf32 warp MMA: D(16x8) += A(16x8) * B(8x8)
__device__ __forceinline__ void mma_tf32(float* d, const uint32_t* a, const uint32_t* b) {
    asm volatile(
        "mma.sync.aligned.m16n8k8.row.col.f32.tf32.tf32.f32 "
        "{%0,%1,%2,%3}, {%4,%5,%6,%7}, {%8,%9}, {%0,%1,%2,%3};"
        : "+f"(d[0]), "+f"(d[1]), "+f"(d[2]), "+f"(d[3])
        : "r"(a[0]), "r"(a[1]), "r"(a[2]), "r"(a[3]), "r"(b[0]), "r"(b[1]));
}

// fp32 -> tf32 round-to-nearest (unbiased).
__device__ __forceinline__ uint32_t to_tf32(float f) {
    uint32_t h;
    asm("cvt.rna.tf32.f32 %0, %1;" : "=r"(h) : "f"(f));
    return h;
}
__device__ __forceinline__ float round_tf32(float f) {
    return __uint_as_float(to_tf32(f));
}

// ---------------- kernel: transpose + tf32-round weights --------------------
__global__ void transpose_w_kernel(const float* __restrict__ W, int N, int which)
{
    __shared__ float t[32][33];
    float* Wt = which ? g_wt_proj : g_wt_qkv;
    int n0 = blockIdx.x * 32, k0 = blockIdx.y * 32;
    int tx = threadIdx.x, ty = threadIdx.y;    // 32 x 8
    #pragma unroll
    for (int j = 0; j < 4; ++j)
        t[ty + j*8][tx] = W[(size_t)(k0 + ty + j*8) * N + n0 + tx];
    __syncthreads();
    #pragma unroll
    for (int j = 0; j < 4; ++j)
        Wt[(size_t)(n0 + ty + j*8) * 256 + k0 + tx] = round_tf32(t[tx][ty + j*8]);
}

// ---------------- kernel: build per-head relative-position bias -------------
__global__ void bias_build_kernel(const float* __restrict__ table,
                                  const int*   __restrict__ rel)
{
    int t = blockIdx.x * blockDim.x + threadIdx.x;
    if (t < NHEAD * NN2) {
        int h  = t / NN2;
        int ij = t - h * NN2;
        g_bias[t] = table[rel[ij] * NHEAD + h];
    }
}

// ---------------- 1xTF32 mma.sync GEMM: 128x128 tile, K=256 -----------------
// Grid: (n_blocks, m_blocks) — n fast so consecutive CTAs share A rows (L2).
#define GPITCH 36
#define TILE_F (128 * GPITCH)                 // 4608 floats
#define BUF_F  (2 * TILE_F)                   // 9216 floats per buffer
#define GEMM_SMEM (2 * BUF_F * 4)             // 73728 bytes

template<bool IS_QKV>
__global__ void __launch_bounds__(256, 2)
gemm_mma_kernel(const float* __restrict__ Aq,   // QKV: x; proj: unused
                const float* __restrict__ bias,
                float* __restrict__ out)        // proj: d_out; QKV: unused
{
    extern __shared__ float smf[];
    uint32_t sb = smem_to_u32(smf);
    const int tid = threadIdx.x;
    const int wid = tid >> 5, lane = tid & 31;
    const int g = lane >> 2, tg = lane & 3;
    const int bm = blockIdx.y * 128;      // m = slow dim
    const int bn = blockIdx.x * 128;      // n = fast dim (A reuse across wave)

    const float* A  = IS_QKV ? Aq : g_o;
    const float* Bt = IS_QKV ? g_wt_qkv : g_wt_proj;
    const int K = 256;

    const int r_  = tid >> 3;
    const int c4_ = tid & 7;

    float acc[4][4][4];
    #pragma unroll
    for (int am = 0; am < 4; ++am)
        #pragma unroll
        for (int an = 0; an < 4; ++an)
            #pragma unroll
            for (int j = 0; j < 4; ++j) acc[am][an][j] = 0.0f;

    auto issue = [&](int c, int buf) {
        int k0 = c * 32;
        uint32_t base = sb + (uint32_t)buf * (BUF_F * 4);
        #pragma unroll
        for (int i = 0; i < 4; ++i) {
            int r = r_ + i * 32;
            cp_async16(base + (uint32_t)(r * GPITCH * 4 + c4_ * 16),
                       A + (size_t)(bm + r) * K + k0 + c4_ * 4);
        }
        #pragma unroll
        for (int i = 0; i < 4; ++i) {
            int r = r_ + i * 32;
            cp_async16(base + (uint32_t)(TILE_F * 4 + r * GPITCH * 4 + c4_ * 16),
                       Bt + (size_t)(bn + r) * K + k0 + c4_ * 4);
        }
    };

    issue(0, 0);
    CP_COMMIT();

    const int mw = (wid >> 2) * 64;
    const int nw = (wid & 3) * 32;

    #pragma unroll 1
    for (int c = 0; c < 8; ++c) {
        if (c + 1 < 8) { issue(c + 1, (c + 1) & 1); CP_COMMIT(); CP_WAIT(1); }
        else           { CP_WAIT(0); }
        __syncthreads();

        const float* As = smf + (c & 1) * BUF_F;
        const float* Bs = As + TILE_F;

        #pragma unroll
        for (int s = 0; s < 4; ++s) {
            int k0 = s * 8 + tg;
            uint32_t b[4][2];
            #pragma unroll
            for (int an = 0; an < 4; ++an) {
                int base = (nw + 8 * an + g) * GPITCH + k0;
                b[an][0] = __float_as_uint(Bs[base]);      // pre-rounded weights
                b[an][1] = __float_as_uint(Bs[base + 4]);
            }
            #pragma unroll
            for (int am = 0; am < 4; ++am) {
                int base = (mw + 16 * am + g) * GPITCH + k0;
                uint32_t a[4];
                a[0] = to_tf32(As[base]);
                a[1] = to_tf32(As[base + 8 * GPITCH]);
                a[2] = to_tf32(As[base + 4]);
                a[3] = to_tf32(As[base + 8 * GPITCH + 4]);
                #pragma unroll
                for (int an = 0; an < 4; ++an)
                    mma_tf32(acc[am][an], a, b[an]);
            }
        }
        __syncthreads();
    }

    // -------- epilogue --------
    #pragma unroll
    for (int am = 0; am < 4; ++am) {
        #pragma unroll
        for (int half = 0; half < 2; ++half) {
            int m = bm + mw + 16 * am + g + 8 * half;
            if (IS_QKV) {
                int bwin = m / NTOK;
                int nn   = m - bwin * NTOK;
                #pragma unroll
                for (int an = 0; an < 4; ++an) {
                    int gcol = bn + nw + 8 * an + 2 * tg;
                    int sel  = gcol >> 8;
                    int h    = (gcol >> 5) & 7;
                    int d    = gcol & 31;
                    float* dst = (sel == 0 ? g_q : (sel == 1 ? g_k : g_v))
                               + (((size_t)bwin * NHEAD + h) * NTOK + nn) * HD + d;
                    float sc = (sel == 0) ? QK_SCALE : 1.0f;
                    float2 v;
                    v.x = (acc[am][an][2*half+0] + bias[gcol+0]) * sc;
                    v.y = (acc[am][an][2*half+1] + bias[gcol+1]) * sc;
                    *(float2*)dst = v;
                }
            } else {
                #pragma unroll
                for (int an = 0; an < 4; ++an) {
                    int gcol = bn + nw + 8 * an + 2 * tg;
                    float2 v;
                    v.x = acc[am][an][2*half+0] + bias[gcol+0];
                    v.y = acc[am][an][2*half+1] + bias[gcol+1];
                    *(float2*)(out + (size_t)m * DIMC + gcol) = v;
                }
            }
        }
    }
}

// ---------------- kernel: fused windowed attention (R7 fp32 version) --------
#define SM_Q 0
#define SM_K 3234
#define SM_S 6468
#define ATTN_SMEM_BYTES (16072 * 4)

__global__ void __launch_bounds__(256) attn_kernel(const float* __restrict__ mask)
{
    extern __shared__ float sm[];
    float* Qs = sm + SM_Q;
    float* Ks = sm + SM_K;
    float* S  = sm + SM_S;

    int bid = blockIdx.x;
    int b = bid >> 3, h = bid & 7;
    int w = b & (NWIN - 1);
    int tid = threadIdx.x;
    int tx = tid & 15, ty = tid >> 4;

    const float* qp = g_q + (size_t)bid * (NTOK * HD);
    const float* kp = g_k + (size_t)bid * (NTOK * HD);
    const float* vp = g_v + (size_t)bid * (NTOK * HD);

    for (int t = tid; t < (NTOK * HD) / 4; t += 256) {
        float4 q4 = ((const float4*)qp)[t];
        float4 k4 = ((const float4*)kp)[t];
        int i = t >> 3, seg = (t & 7) * 4;
        float* qd = Qs + i*33 + seg;
        float* kd = Ks + i*33 + seg;
        qd[0]=q4.x; qd[1]=q4.y; qd[2]=q4.z; qd[3]=q4.w;
        kd[0]=k4.x; kd[1]=k4.y; kd[2]=k4.z; kd[3]=k4.w;
    }
    __syncthreads();

    float acc[7][7];
    #pragma unroll
    for (int r = 0; r < 7; ++r)
        #pragma unroll
        for (int s2 = 0; s2 < 7; ++s2) acc[r][s2] = 0.0f;

    for (int kk = 0; kk < HD; ++kk) {
        float qv[7], kv[7];
        #pragma unroll
        for (int r = 0; r < 7; ++r) {
            int i = ty + 16*r; i = (i < NTOK) ? i : (NTOK - 1);
            qv[r] = Qs[i*33 + kk];
        }
        #pragma unroll
        for (int s2 = 0; s2 < 7; ++s2) {
            int j = tx + 16*s2; j = (j < NTOK) ? j : (NTOK - 1);
            kv[s2] = Ks[j*33 + kk];
        }
        #pragma unroll
        for (int r = 0; r < 7; ++r)
            #pragma unroll
            for (int s2 = 0; s2 < 7; ++s2)
                acc[r][s2] = fmaf(qv[r], kv[s2], acc[r][s2]);
    }

    const float* bptr = g_bias + h * NN2;
    const float* mptr = mask + w * NN2;
    #pragma unroll
    for (int r = 0; r < 7; ++r) {
        int i = ty + 16*r;
        if (i < NTOK) {
            #pragma unroll
            for (int s2 = 0; s2 < 7; ++s2) {
                int j = tx + 16*s2;
                if (j < NTOK)
                    S[i*NTOK + j] = acc[r][s2] + bptr[i*NTOK + j] + mptr[i*NTOK + j];
            }
        }
    }
    __syncthreads();

    for (int t = tid; t < (NTOK * HD) / 4; t += 256) {
        float4 v4 = ((const float4*)vp)[t];
        int i = t >> 3, seg = (t & 7) * 4;
        float* vd = Qs + i*33 + seg;
        vd[0]=v4.x; vd[1]=v4.y; vd[2]=v4.z; vd[3]=v4.w;
    }

    int warp = tid >> 5, lane = tid & 31;
    for (int r = warp; r < NTOK; r += 8) {
        float* row = S + r * NTOK;
        float v0 = row[lane];
        float v1 = row[32 + lane];
        float v2 = row[64 + lane];
        float v3 = (lane < 2) ? row[96 + lane] : -1e30f;
        float mx = fmaxf(fmaxf(v0, v1), fmaxf(v2, v3));
        #pragma unroll
        for (int o = 16; o > 0; o >>= 1) mx = fmaxf(mx, __shfl_xor_sync(0xffffffffu, mx, o));
        float e0 = __expf(v0 - mx), e1 = __expf(v1 - mx), e2 = __expf(v2 - mx);
        float e3 = (lane < 2) ? __expf(v3 - mx) : 0.0f;
        float sum = e0 + e1 + e2 + e3;
        #pragma unroll
        for (int o = 16; o > 0; o >>= 1) sum += __shfl_xor_sync(0xffffffffu, sum, o);
        float inv = 1.0f / sum;
        row[lane]      = e0 * inv;
        row[32 + lane] = e1 * inv;
        row[64 + lane] = e2 * inv;
        if (lane < 2) row[96 + lane] = e3 * inv;
    }
    __syncthreads();

    float o0[7], o1[7];
    #pragma unroll
    for (int r = 0; r < 7; ++r) { o0[r] = 0.0f; o1[r] = 0.0f; }

    for (int j = 0; j < NTOK; ++j) {
        float v0 = Qs[j*33 + tx];
        float v1 = Qs[j*33 + 16 + tx];
        #pragma unroll
        for (int r = 0; r < 7; ++r) {
            int i = ty + 16*r;
            if (i < NTOK) {
                float p = S[i*NTOK + j];
                o0[r] = fmaf(p, v0, o0[r]);
                o1[r] = fmaf(p, v1, o1[r]);
            }
        }
    }

    float* op = g_o + (size_t)b * NTOK * DIMC + h * HD;
    #pragma unroll
    for (int r = 0; r < 7; ++r) {
        int i = ty + 16*r;
        if (i < NTOK) {
            op[(size_t)i * DIMC + tx]      = o0[r];
            op[(size_t)i * DIMC + 16 + tx] = o1[r];
        }
    }
}

// ---------------- launch -----------------------------------------------------
extern "C" void kernel_launch(void* const* d_in, const int* in_sizes, int n_in,
                              void* d_out, int out_size)
{
    const float* x          = (const float*)d_in[0];
    const float* mask       = (const float*)d_in[1];
    const float* qkv_w      = (const float*)d_in[2];
    const float* qkv_b      = (const float*)d_in[3];
    const float* proj_w     = (const float*)d_in[4];
    const float* proj_b     = (const float*)d_in[5];
    const float* bias_table = (const float*)d_in[6];
    const int*   rel_index  = (const int*)d_in[7];
    float* out = (float*)d_out;

    cudaFuncSetAttribute((const void*)gemm_mma_kernel<true>,
                         cudaFuncAttributeMaxDynamicSharedMemorySize, GEMM_SMEM);
    cudaFuncSetAttribute((const void*)gemm_mma_kernel<false>,
                         cudaFuncAttributeMaxDynamicSharedMemorySize, GEMM_SMEM);
    cudaFuncSetAttribute((const void*)attn_kernel,
                         cudaFuncAttributeMaxDynamicSharedMemorySize, ATTN_SMEM_BYTES);

    transpose_w_kernel<<<dim3(24, 8), dim3(32, 8)>>>(qkv_w, 768, 0);
    transpose_w_kernel<<<dim3(8, 8),  dim3(32, 8)>>>(proj_w, 256, 1);
    bias_build_kernel<<<(NHEAD * NN2 + 255) / 256, 256>>>(bias_table, rel_index);

    // n-blocks fast (x), m-blocks slow (y): consecutive CTAs reuse A via L2
    gemm_mma_kernel<true><<<dim3(6, 1568), 256, GEMM_SMEM>>>(x, qkv_b, nullptr);

    attn_kernel<<<BQ * NHEAD, 256, ATTN_SMEM_BYTES>>>(mask);

    gemm_mma_kernel<false><<<dim3(2, 1568), 256, GEMM_SMEM>>>(nullptr, proj_b, out);
}